// round 1
// baseline (speedup 1.0000x reference)
#include <cuda_runtime.h>

// ---------------- scratch (device globals; no allocation) ----------------
__device__ float g_off[8 * 18 * 128 * 128];   // offset conv output, 9.4 MB
__device__ float g_wT[576 * 64];              // deform_w transposed to [c*9+k][o]

// ---------------- prep: transpose deform weights ----------------
__global__ void transpose_w_kernel(const float* __restrict__ dw) {
    int i = blockIdx.x * 256 + threadIdx.x;
    if (i < 576 * 64) {
        int o = i / 576, ck = i % 576;
        g_wT[ck * 64 + o] = dw[i];
    }
}

// ---------------- stage 1: 3x3 conv x(64ch) -> off(18ch), SAME padding ----
__global__ __launch_bounds__(256) void offset_conv_kernel(
    const float* __restrict__ x, const float* __restrict__ ow,
    const float* __restrict__ ob)
{
    __shared__ float xt[18 * 18];
    __shared__ __align__(16) float ws[9][20];   // [tap][ch], ch padded 18->20

    int tid = threadIdx.x;
    int b = blockIdx.z;
    int ty = blockIdx.y * 16, tx = blockIdx.x * 16;

    float acc[20];
#pragma unroll
    for (int i = 0; i < 20; i++) acc[i] = 0.f;

    // zero the pad columns once (never overwritten afterwards)
    for (int t = tid; t < 180; t += 256) ((float*)ws)[t] = 0.f;

    const float* xb = x + (size_t)b * 64 * 16384;

    for (int c = 0; c < 64; c++) {
        __syncthreads();  // guard smem reuse from previous iteration
        for (int t = tid; t < 324; t += 256) {
            int gy = ty - 1 + t / 18, gx = tx - 1 + t % 18;
            float v = 0.f;
            if ((unsigned)gy < 128u && (unsigned)gx < 128u)
                v = xb[c * 16384 + gy * 128 + gx];
            xt[t] = v;
        }
        for (int t = tid; t < 162; t += 256) {
            int ch = t / 9, tap = t % 9;
            ws[tap][ch] = ow[ch * 576 + c * 9 + tap];
        }
        __syncthreads();

        int yy = tid >> 4, xx = tid & 15;
#pragma unroll
        for (int tap = 0; tap < 9; tap++) {
            float xv = xt[(yy + tap / 3) * 18 + xx + tap % 3];
#pragma unroll
            for (int j = 0; j < 5; j++) {
                float4 w4 = *(const float4*)&ws[tap][j * 4];
                acc[j * 4 + 0] = fmaf(xv, w4.x, acc[j * 4 + 0]);
                acc[j * 4 + 1] = fmaf(xv, w4.y, acc[j * 4 + 1]);
                acc[j * 4 + 2] = fmaf(xv, w4.z, acc[j * 4 + 2]);
                acc[j * 4 + 3] = fmaf(xv, w4.w, acc[j * 4 + 3]);
            }
        }
    }

    int yy = tid >> 4, xx = tid & 15;
    int y = ty + yy, xg = tx + xx;
#pragma unroll
    for (int ch = 0; ch < 18; ch++)
        g_off[(b * 18 + ch) * 16384 + y * 128 + xg] = acc[ch] + ob[ch];
}

// ---------------- stage 2: fused bilinear gather + 64x64x576 contraction ---
// Block = 8x8 pixel tile of one batch image. 256 threads.
// Micro-GEMM: M=64 outputs x N=64 pixels, K=9 per channel chunk, 64 chunks.
__global__ __launch_bounds__(256) void deform_main_kernel(
    const float* __restrict__ x, const float* __restrict__ db,
    float* __restrict__ out)
{
    __shared__ float s_w00[576], s_w01[576], s_w10[576], s_w11[576];
    __shared__ int   s_iy[576], s_ix[576];
    __shared__ float s_T[400];                    // 20x20 x-tile (halo 6)
    __shared__ __align__(16) float s_S[576];      // sampled [k][pixel]
    __shared__ __align__(16) float s_W[576];      // weights [k][o]

    int tid = threadIdx.x;
    int b  = blockIdx.z;
    int ty = blockIdx.y * 8, tx = blockIdx.x * 8;

    // --- precompute sampling positions/weights for all 9 taps x 64 pixels ---
    for (int e = tid; e < 576; e += 256) {
        int k = e >> 6, p = e & 63;
        int yy = ty + (p >> 3), xx = tx + (p & 7);
        float dy = g_off[(b * 18 + 2 * k)     * 16384 + yy * 128 + xx];
        float dx = g_off[(b * 18 + 2 * k + 1) * 16384 + yy * 128 + xx];
        float py = (float)(yy + (k / 3) - 1) + dy;
        float px = (float)(xx + (k % 3) - 1) + dx;
        float fy = floorf(py), fx = floorf(px);
        float wy = py - fy, wx = px - fx;
        s_w00[e] = (1.f - wy) * (1.f - wx);
        s_w01[e] = (1.f - wy) * wx;
        s_w10[e] = wy * (1.f - wx);
        s_w11[e] = wy * wx;
        s_iy[e] = (int)fy;
        s_ix[e] = (int)fx;
    }

    float acc[4][4];
#pragma unroll
    for (int i = 0; i < 4; i++)
#pragma unroll
        for (int j = 0; j < 4; j++) acc[i][j] = 0.f;

    int tm = tid >> 4, tn = tid & 15;
    const float* xb = x + (size_t)b * 64 * 16384;

    for (int c = 0; c < 64; c++) {
        __syncthreads();  // previous GEMM done before overwriting tiles
        // load x tile (20x20, halo 6, zero outside image)
        for (int t = tid; t < 400; t += 256) {
            int gy = ty - 6 + t / 20, gx = tx - 6 + t % 20;
            float v = 0.f;
            if ((unsigned)gy < 128u && (unsigned)gx < 128u)
                v = xb[c * 16384 + gy * 128 + gx];
            s_T[t] = v;
        }
        // load weight slab [k][o] for this channel (coalesced)
        for (int t = tid; t < 576; t += 256)
            s_W[t] = g_wT[c * 576 + t];
        __syncthreads();

        // build sampled tile S[k][p]
        for (int e = tid; e < 576; e += 256) {
            int iy = s_iy[e], ix = s_ix[e];
            int ly = iy - (ty - 6), lx = ix - (tx - 6);
            float v;
            if ((unsigned)ly < 19u && (unsigned)lx < 19u) {
                const float* t0 = &s_T[ly * 20 + lx];
                v = s_w00[e] * t0[0]  + s_w01[e] * t0[1]
                  + s_w10[e] * t0[20] + s_w11[e] * t0[21];
            } else {
                // rare fallback: corner outside tile window -> global, masked
                const float* xc = xb + c * 16384;
                float v00 = ((unsigned)iy < 128u && (unsigned)ix < 128u)
                          ? xc[iy * 128 + ix] : 0.f;
                float v01 = ((unsigned)iy < 128u && (unsigned)(ix + 1) < 128u)
                          ? xc[iy * 128 + ix + 1] : 0.f;
                float v10 = ((unsigned)(iy + 1) < 128u && (unsigned)ix < 128u)
                          ? xc[(iy + 1) * 128 + ix] : 0.f;
                float v11 = ((unsigned)(iy + 1) < 128u && (unsigned)(ix + 1) < 128u)
                          ? xc[(iy + 1) * 128 + ix + 1] : 0.f;
                v = s_w00[e] * v00 + s_w01[e] * v01
                  + s_w10[e] * v10 + s_w11[e] * v11;
            }
            s_S[e] = v;
        }
        __syncthreads();

        // register-tiled GEMM: 9 K-steps, 4x4 micro-tile per thread
#pragma unroll
        for (int k = 0; k < 9; k++) {
            float4 a  = *(const float4*)&s_W[k * 64 + tm * 4];
            float4 bb = *(const float4*)&s_S[k * 64 + tn * 4];
            acc[0][0] = fmaf(a.x, bb.x, acc[0][0]);
            acc[0][1] = fmaf(a.x, bb.y, acc[0][1]);
            acc[0][2] = fmaf(a.x, bb.z, acc[0][2]);
            acc[0][3] = fmaf(a.x, bb.w, acc[0][3]);
            acc[1][0] = fmaf(a.y, bb.x, acc[1][0]);
            acc[1][1] = fmaf(a.y, bb.y, acc[1][1]);
            acc[1][2] = fmaf(a.y, bb.z, acc[1][2]);
            acc[1][3] = fmaf(a.y, bb.w, acc[1][3]);
            acc[2][0] = fmaf(a.z, bb.x, acc[2][0]);
            acc[2][1] = fmaf(a.z, bb.y, acc[2][1]);
            acc[2][2] = fmaf(a.z, bb.z, acc[2][2]);
            acc[2][3] = fmaf(a.z, bb.w, acc[2][3]);
            acc[3][0] = fmaf(a.w, bb.x, acc[3][0]);
            acc[3][1] = fmaf(a.w, bb.y, acc[3][1]);
            acc[3][2] = fmaf(a.w, bb.z, acc[3][2]);
            acc[3][3] = fmaf(a.w, bb.w, acc[3][3]);
        }
    }

    // epilogue: bias + relu, vectorized store (4 consecutive w per thread)
    int row = ty + (tn >> 1);
    int col = tx + (tn & 1) * 4;
#pragma unroll
    for (int i = 0; i < 4; i++) {
        int o = tm * 4 + i;
        float bias = db[o];
        float4 r;
        r.x = fmaxf(acc[i][0] + bias, 0.f);
        r.y = fmaxf(acc[i][1] + bias, 0.f);
        r.z = fmaxf(acc[i][2] + bias, 0.f);
        r.w = fmaxf(acc[i][3] + bias, 0.f);
        *(float4*)&out[(b * 64 + o) * 16384 + row * 128 + col] = r;
    }
}

// ---------------- launch ----------------
extern "C" void kernel_launch(void* const* d_in, const int* in_sizes, int n_in,
                              void* d_out, int out_size) {
    const float* x        = (const float*)d_in[0];  // (8,64,128,128)
    const float* offset_w = (const float*)d_in[1];  // (18,64,3,3)
    const float* offset_b = (const float*)d_in[2];  // (18,)
    const float* deform_w = (const float*)d_in[3];  // (64,64,3,3)
    const float* deform_b = (const float*)d_in[4];  // (64,)
    float* out = (float*)d_out;                     // (8,64,128,128)

    transpose_w_kernel<<<144, 256>>>(deform_w);
    offset_conv_kernel<<<dim3(8, 8, 8), 256>>>(x, offset_w, offset_b);
    deform_main_kernel<<<dim3(16, 16, 8), 256>>>(x, deform_b, out);
}

// round 3
// speedup vs baseline: 1.0500x; 1.0500x over previous
#include <cuda_runtime.h>
#include <cstdint>

// ===================== device scratch (no allocation) =====================
__device__ float g_off[8 * 18 * 128 * 128];   // offset conv output
__device__ float g_whi[8 * 72 * 64];          // deform_w hi tf32: [chunk][kk][o]
__device__ float g_wlo[8 * 72 * 64];          // deform_w lo tf32

// ===================== helpers =====================
__device__ __forceinline__ uint32_t f2tf32(float f) {
    uint32_t r;
    asm("cvt.rna.tf32.f32 %0, %1;" : "=r"(r) : "f"(f));
    return r;
}
__device__ __forceinline__ void mma8(float* d,
                                     uint32_t a0, uint32_t a1, uint32_t a2, uint32_t a3,
                                     uint32_t b0, uint32_t b1) {
    asm volatile(
        "mma.sync.aligned.m16n8k8.row.col.f32.tf32.tf32.f32 "
        "{%0,%1,%2,%3}, {%4,%5,%6,%7}, {%8,%9}, {%0,%1,%2,%3};"
        : "+f"(d[0]), "+f"(d[1]), "+f"(d[2]), "+f"(d[3])
        : "r"(a0), "r"(a1), "r"(a2), "r"(a3), "r"(b0), "r"(b1));
}

// ===================== prep: split deform weights into tf32 hi/lo ==========
__global__ void wprep_kernel(const float* __restrict__ dw) {
    int i = blockIdx.x * 256 + threadIdx.x;   // 8*72*64 = 36864
    if (i < 36864) {
        int j = i / 4608;
        int r = i - j * 4608;
        int kk = r >> 6, o = r & 63;
        int c = j * 8 + kk / 9;
        int tap = kk % 9;
        float w = dw[o * 576 + c * 9 + tap];
        uint32_t hi = f2tf32(w);
        uint32_t lo = f2tf32(w - __uint_as_float(hi));
        g_whi[i] = __uint_as_float(hi);
        g_wlo[i] = __uint_as_float(lo);
    }
}

// ===================== stage 1: 3x3 conv x(64ch) -> off(18ch) ==============
__global__ __launch_bounds__(256) void offset_conv_kernel(
    const float* __restrict__ x, const float* __restrict__ ow,
    const float* __restrict__ ob)
{
    __shared__ float xt[18 * 18];
    __shared__ __align__(16) float ws[9][20];

    int tid = threadIdx.x;
    int b = blockIdx.z;
    int ty = blockIdx.y * 16, tx = blockIdx.x * 16;

    float acc[20];
#pragma unroll
    for (int i = 0; i < 20; i++) acc[i] = 0.f;
    for (int t = tid; t < 180; t += 256) ((float*)ws)[t] = 0.f;

    const float* xb = x + (size_t)b * 64 * 16384;

    for (int c = 0; c < 64; c++) {
        __syncthreads();
        for (int t = tid; t < 324; t += 256) {
            int gy = ty - 1 + t / 18, gx = tx - 1 + t % 18;
            float v = 0.f;
            if ((unsigned)gy < 128u && (unsigned)gx < 128u)
                v = xb[c * 16384 + gy * 128 + gx];
            xt[t] = v;
        }
        for (int t = tid; t < 162; t += 256) {
            int ch = t / 9, tap = t % 9;
            ws[tap][ch] = ow[ch * 576 + c * 9 + tap];
        }
        __syncthreads();

        int yy = tid >> 4, xx = tid & 15;
#pragma unroll
        for (int tap = 0; tap < 9; tap++) {
            float xv = xt[(yy + tap / 3) * 18 + xx + tap % 3];
#pragma unroll
            for (int jj = 0; jj < 5; jj++) {
                float4 w4 = *(const float4*)&ws[tap][jj * 4];
                acc[jj * 4 + 0] = fmaf(xv, w4.x, acc[jj * 4 + 0]);
                acc[jj * 4 + 1] = fmaf(xv, w4.y, acc[jj * 4 + 1]);
                acc[jj * 4 + 2] = fmaf(xv, w4.z, acc[jj * 4 + 2]);
                acc[jj * 4 + 3] = fmaf(xv, w4.w, acc[jj * 4 + 3]);
            }
        }
    }

    int yy = tid >> 4, xx = tid & 15;
    int y = ty + yy, xg = tx + xx;
#pragma unroll
    for (int ch = 0; ch < 18; ch++)
        g_off[(b * 18 + ch) * 16384 + y * 128 + xg] = acc[ch] + ob[ch];
}

// ===================== SMEM layout (floats) =====================
// [0]     bias           64
// [64]    swy            1152
// [1216]  swx            1152
// [2368]  spk (uint)     1152
// [3520]  xt             8*630 = 5040
// [8560]  whi            72*72 = 5184  (row stride 72 -> conflict-free)
// [13744] wlo            5184
// total 18928 floats = 75712 B
#define SM_BIAS 0
#define SM_WY   64
#define SM_WX   1216
#define SM_PK   2368
#define SM_XT   3520
#define SM_WHI  8560
#define SM_WLO  13744
#define SMEM_FLOATS 18928

// ===================== bilinear sample of one A element =====================
__device__ __forceinline__ float sample_one(
    const float* __restrict__ xt, const float* __restrict__ swy,
    const float* __restrict__ swx, const uint32_t* __restrict__ spk,
    const float* __restrict__ xc, int kk, int p, int ty, int tx)
{
    int c_local = kk / 9;
    int tap = kk - c_local * 9;
    int idx = tap * 128 + p;
    float wy = swy[idx], wx = swx[idx];
    uint32_t pk = spk[idx];
    int iy = (int)(pk >> 16) - 1024;
    int ix = (int)(pk & 0xffffu) - 1024;
    float oy = 1.f - wy, ox = 1.f - wx;
    float w00 = oy * ox, w01 = oy * wx, w10 = wy * ox, w11 = wy * wx;
    int ly = iy - (ty - 6), lx = ix - (tx - 6);
    if ((unsigned)ly < 20u && (unsigned)lx < 29u) {
        const float* t0 = &xt[c_local * 630 + ly * 30 + lx];
        return w00 * t0[0] + w01 * t0[1] + w10 * t0[30] + w11 * t0[31];
    }
    const float* xp = xc + c_local * 16384;
    float v00 = ((unsigned)iy < 128u && (unsigned)ix < 128u)
              ? xp[iy * 128 + ix] : 0.f;
    float v01 = ((unsigned)iy < 128u && (unsigned)(ix + 1) < 128u)
              ? xp[iy * 128 + ix + 1] : 0.f;
    float v10 = ((unsigned)(iy + 1) < 128u && (unsigned)ix < 128u)
              ? xp[(iy + 1) * 128 + ix] : 0.f;
    float v11 = ((unsigned)(iy + 1) < 128u && (unsigned)(ix + 1) < 128u)
              ? xp[(iy + 1) * 128 + ix + 1] : 0.f;
    return w00 * v00 + w01 * v01 + w10 * v10 + w11 * v11;
}

// ===================== stage 2: gather + tf32 mma.sync (3-split) ===========
// Block: 16x8 pixel tile (M=128 pixels), 256 threads = 8 warps.
// Warp w owns M-tile [w*16, w*16+16). N = 64 outputs (8 n-tiles).
// K = 576 processed as 8 chunks of 8 channels (72 = 9 mma k-steps each).
__global__ __launch_bounds__(256) void deform_main_kernel(
    const float* __restrict__ x, const float* __restrict__ db,
    float* __restrict__ out)
{
    extern __shared__ float smf[];
    float*    sbias = smf + SM_BIAS;
    float*    swy   = smf + SM_WY;
    float*    swx   = smf + SM_WX;
    uint32_t* spk   = (uint32_t*)(smf + SM_PK);
    float*    xt    = smf + SM_XT;
    float*    whi_s = smf + SM_WHI;
    float*    wlo_s = smf + SM_WLO;

    const int tid = threadIdx.x;
    const int w = tid >> 5, lane = tid & 31;
    const int gid = lane >> 2, tig = lane & 3;
    const int b = blockIdx.z;
    const int ty = blockIdx.y * 8, tx = blockIdx.x * 16;

    if (tid < 64) sbias[tid] = db[tid];

    // ---- prologue: bilinear weights/corners for 9 taps x 128 pixels ----
    for (int e = tid; e < 1152; e += 256) {
        int k = e >> 7, p = e & 127;
        int yy = ty + (p >> 4), xx = tx + (p & 15);
        float dy = g_off[((size_t)b * 18 + 2 * k) * 16384 + yy * 128 + xx];
        float dx = g_off[((size_t)b * 18 + 2 * k + 1) * 16384 + yy * 128 + xx];
        float py = (float)(yy + (k / 3) - 1) + dy;
        float px = (float)(xx + (k % 3) - 1) + dx;
        float fy = floorf(py), fx = floorf(px);
        swy[e] = py - fy;
        swx[e] = px - fx;
        fy = fminf(fmaxf(fy, -900.f), 900.f);
        fx = fminf(fmaxf(fx, -900.f), 900.f);
        int iy = (int)fy, ix = (int)fx;
        spk[e] = ((uint32_t)(iy + 1024) << 16) | (uint32_t)(ix + 1024);
    }

    float acc[8][4];
#pragma unroll
    for (int n = 0; n < 8; n++)
#pragma unroll
        for (int i = 0; i < 4; i++) acc[n][i] = 0.f;

    const int m_base = w * 16;
    const int p0 = m_base + gid;
    const float* xb = x + (size_t)b * 64 * 16384;

    for (int j = 0; j < 8; j++) {
        __syncthreads();   // protect xt / W from previous chunk's readers
        const float* xc = xb + (size_t)j * 8 * 16384;
        // x tiles: 8 channels x 21 rows x 30 cols (halo 6)
        for (int t = tid; t < 5040; t += 256) {
            int cc = t / 630, r = t - cc * 630;
            int rr = r / 30, cl = r - rr * 30;
            int gy = ty - 6 + rr, gx = tx - 6 + cl;
            float v = 0.f;
            if ((unsigned)gy < 128u && (unsigned)gx < 128u)
                v = xc[cc * 16384 + gy * 128 + gx];
            xt[t] = v;
        }
        // weight chunk into SMEM, padded row stride 72
        for (int e = tid; e < 4608; e += 256) {
            int kk = e >> 6, o = e & 63;
            whi_s[kk * 72 + o] = g_whi[j * 4608 + e];
            wlo_s[kk * 72 + o] = g_wlo[j * 4608 + e];
        }
        __syncthreads();

#pragma unroll
        for (int kt = 0; kt < 9; kt++) {
            int kkA = kt * 8 + tig;
            float a0f = sample_one(xt, swy, swx, spk, xc, kkA,     p0,     ty, tx);
            float a1f = sample_one(xt, swy, swx, spk, xc, kkA,     p0 + 8, ty, tx);
            float a2f = sample_one(xt, swy, swx, spk, xc, kkA + 4, p0,     ty, tx);
            float a3f = sample_one(xt, swy, swx, spk, xc, kkA + 4, p0 + 8, ty, tx);
            uint32_t ah0 = f2tf32(a0f), ah1 = f2tf32(a1f);
            uint32_t ah2 = f2tf32(a2f), ah3 = f2tf32(a3f);
            uint32_t al0 = f2tf32(a0f - __uint_as_float(ah0));
            uint32_t al1 = f2tf32(a1f - __uint_as_float(ah1));
            uint32_t al2 = f2tf32(a2f - __uint_as_float(ah2));
            uint32_t al3 = f2tf32(a3f - __uint_as_float(ah3));

            const float* Bh = &whi_s[(kt * 8 + tig) * 72 + gid];
            const float* Bl = &wlo_s[(kt * 8 + tig) * 72 + gid];
#pragma unroll
            for (int nt = 0; nt < 8; nt++) {
                uint32_t bh0 = __float_as_uint(Bh[nt * 8]);
                uint32_t bh1 = __float_as_uint(Bh[4 * 72 + nt * 8]);
                uint32_t bl0 = __float_as_uint(Bl[nt * 8]);
                uint32_t bl1 = __float_as_uint(Bl[4 * 72 + nt * 8]);
                mma8(acc[nt], ah0, ah1, ah2, ah3, bh0, bh1);
                mma8(acc[nt], al0, al1, al2, al3, bh0, bh1);
                mma8(acc[nt], ah0, ah1, ah2, ah3, bl0, bl1);
            }
        }
    }

    // ---- epilogue: bias + relu ----
    const int pA = p0, pB = p0 + 8;
    const int yA = ty + (pA >> 4), xA = tx + (pA & 15);
    const int yB = ty + (pB >> 4), xB = tx + (pB & 15);
    float* ob = out + ((size_t)b * 64) * 16384;
#pragma unroll
    for (int nt = 0; nt < 8; nt++) {
        int o0 = nt * 8 + 2 * tig;
        float bs0 = sbias[o0], bs1 = sbias[o0 + 1];
        ob[(size_t)o0 * 16384 + yA * 128 + xA]       = fmaxf(acc[nt][0] + bs0, 0.f);
        ob[(size_t)(o0 + 1) * 16384 + yA * 128 + xA] = fmaxf(acc[nt][1] + bs1, 0.f);
        ob[(size_t)o0 * 16384 + yB * 128 + xB]       = fmaxf(acc[nt][2] + bs0, 0.f);
        ob[(size_t)(o0 + 1) * 16384 + yB * 128 + xB] = fmaxf(acc[nt][3] + bs1, 0.f);
    }
}

// ===================== launch =====================
extern "C" void kernel_launch(void* const* d_in, const int* in_sizes, int n_in,
                              void* d_out, int out_size) {
    const float* x        = (const float*)d_in[0];  // (8,64,128,128)
    const float* offset_w = (const float*)d_in[1];  // (18,64,3,3)
    const float* offset_b = (const float*)d_in[2];  // (18,)
    const float* deform_w = (const float*)d_in[3];  // (64,64,3,3)
    const float* deform_b = (const float*)d_in[4];  // (64,)
    float* out = (float*)d_out;                     // (8,64,128,128)

    cudaFuncSetAttribute(deform_main_kernel,
                         cudaFuncAttributeMaxDynamicSharedMemorySize,
                         SMEM_FLOATS * 4);

    wprep_kernel<<<144, 256>>>(deform_w);
    offset_conv_kernel<<<dim3(8, 8, 8), 256>>>(x, offset_w, offset_b);
    deform_main_kernel<<<dim3(8, 16, 8), 256, SMEM_FLOATS * 4>>>(x, deform_b, out);
}

// round 4
// speedup vs baseline: 2.0359x; 1.9388x over previous
#include <cuda_runtime.h>
#include <cstdint>

// ===================== device scratch (no allocation) =====================
__device__ float g_off[8 * 18 * 128 * 128];   // offset conv output
__device__ float g_whi[8 * 72 * 64];          // main W, tf32-rounded, [j][kk=tap*8+c][q=(o%8)*8+o/8]
__device__ float g_owhi[8 * 72 * 24];         // offset W hi  [j][kk][o(pad 24)]
__device__ float g_owlo[8 * 72 * 24];         // offset W lo

// ===================== helpers =====================
__device__ __forceinline__ uint32_t f2tf32(float f) {
    uint32_t r;
    asm("cvt.rna.tf32.f32 %0, %1;" : "=r"(r) : "f"(f));
    return r;
}
__device__ __forceinline__ void mma8(float* d,
                                     uint32_t a0, uint32_t a1, uint32_t a2, uint32_t a3,
                                     uint32_t b0, uint32_t b1) {
    asm volatile(
        "mma.sync.aligned.m16n8k8.row.col.f32.tf32.tf32.f32 "
        "{%0,%1,%2,%3}, {%4,%5,%6,%7}, {%8,%9}, {%0,%1,%2,%3};"
        : "+f"(d[0]), "+f"(d[1]), "+f"(d[2]), "+f"(d[3])
        : "r"(a0), "r"(a1), "r"(a2), "r"(a3), "r"(b0), "r"(b1));
}
__device__ __forceinline__ void bilw(float2 m, float& w00, float& w01,
                                     float& w10, float& w11) {
    float oy = 1.f - m.x, ox = 1.f - m.y;
    w00 = oy * ox; w01 = oy * m.y; w10 = m.x * ox; w11 = m.x * m.y;
}
// bilinear sample: interior -> smem tile (stride 30); else masked global
__device__ __forceinline__ float bsample(const float* __restrict__ xt_c,
                                         const float* __restrict__ xg_c,
                                         int toff, int pk,
                                         float w00, float w01, float w10, float w11) {
    if (toff >= 0) {
        const float* t0 = xt_c + toff;
        return w00 * t0[0] + w01 * t0[1] + w10 * t0[30] + w11 * t0[31];
    }
    int iy = (pk >> 16) - 1024;
    int ix = (pk & 0xffff) - 1024;
    float v00 = ((unsigned)iy < 128u && (unsigned)ix < 128u) ? xg_c[iy * 128 + ix] : 0.f;
    float v01 = ((unsigned)iy < 128u && (unsigned)(ix + 1) < 128u) ? xg_c[iy * 128 + ix + 1] : 0.f;
    float v10 = ((unsigned)(iy + 1) < 128u && (unsigned)ix < 128u) ? xg_c[(iy + 1) * 128 + ix] : 0.f;
    float v11 = ((unsigned)(iy + 1) < 128u && (unsigned)(ix + 1) < 128u) ? xg_c[(iy + 1) * 128 + ix + 1] : 0.f;
    return w00 * v00 + w01 * v01 + w10 * v10 + w11 * v11;
}

// ===================== prep: weight layouts =====================
__global__ void wprep_kernel(const float* __restrict__ dw,
                             const float* __restrict__ ow) {
    int i = blockIdx.x * 256 + threadIdx.x;
    if (i < 36864) {           // main W: tf32-rounded, permuted
        int j = i / 4608, r = i - j * 4608;
        int kk = r >> 6, q = r & 63;
        int tap = kk >> 3, c = j * 8 + (kk & 7);
        int o = (q & 7) * 8 + (q >> 3);
        g_whi[i] = __uint_as_float(f2tf32(dw[o * 576 + c * 9 + tap]));
    }
    if (i < 13824) {           // offset W: hi/lo split, padded N=24
        int j = i / 1728, r = i - j * 1728;
        int kk = r / 24, o = r - kk * 24;
        int tap = kk >> 3, c = j * 8 + (kk & 7);
        float wv = (o < 18) ? ow[o * 576 + c * 9 + tap] : 0.f;
        uint32_t hi = f2tf32(wv);
        g_owhi[i] = __uint_as_float(hi);
        g_owlo[i] = __uint_as_float(f2tf32(wv - __uint_as_float(hi)));
    }
}

// ===================== stage 1: offset conv via mma (tf32, W 2-split) ======
// Block 16x16 pixels, 8 warps, warp = 32 pixels (2 m16 tiles). N=24 (18 used).
__global__ __launch_bounds__(256) void offconv_kernel(
    const float* __restrict__ x, const float* __restrict__ ob)
{
    __shared__ float xt[2592];          // 8ch x 18x18 (halo 1)
    __shared__ float wh[1728];          // [kk][24]
    __shared__ float wl[1728];

    int tid = threadIdx.x, w = tid >> 5, lane = tid & 31;
    int gid = lane >> 2, tig = lane & 3;
    int b = blockIdx.z, ty = blockIdx.y * 16, tx = blockIdx.x * 16;
    const float* xb = x + (size_t)b * 64 * 16384;

    float acc0[3][4], acc1[3][4];
#pragma unroll
    for (int n = 0; n < 3; n++)
#pragma unroll
        for (int i = 0; i < 4; i++) { acc0[n][i] = 0.f; acc1[n][i] = 0.f; }

    for (int j = 0; j < 8; j++) {
        __syncthreads();
        const float* xc = xb + (size_t)j * 8 * 16384;
        for (int t = tid; t < 2592; t += 256) {
            int cc = t / 324, r = t - cc * 324;
            int rr = r / 18, cl = r - rr * 18;
            int gy = ty - 1 + rr, gx = tx - 1 + cl;
            float v = 0.f;
            if ((unsigned)gy < 128u && (unsigned)gx < 128u)
                v = xc[cc * 16384 + gy * 128 + gx];
            xt[t] = v;
        }
        for (int t = tid; t < 1728; t += 256) {
            wh[t] = g_owhi[j * 1728 + t];
            wl[t] = g_owlo[j * 1728 + t];
        }
        __syncthreads();

#pragma unroll
        for (int kt = 0; kt < 9; kt++) {
            int dty = kt / 3, dtx = kt - dty * 3;
            const float* a0p = xt + tig * 324 + (2 * w + dty) * 18 + gid + dtx;
            const float* a1p = a0p + 4 * 324;
            uint32_t ah0 = f2tf32(a0p[0]),  ah1 = f2tf32(a0p[8]);
            uint32_t ah2 = f2tf32(a1p[0]),  ah3 = f2tf32(a1p[8]);
            uint32_t gh0 = f2tf32(a0p[18]), gh1 = f2tf32(a0p[26]);
            uint32_t gh2 = f2tf32(a1p[18]), gh3 = f2tf32(a1p[26]);

            int rB = (kt * 8 + tig) * 24 + gid;
#pragma unroll
            for (int nt = 0; nt < 3; nt++) {
                uint32_t bh0 = __float_as_uint(wh[rB + nt * 8]);
                uint32_t bh1 = __float_as_uint(wh[rB + 96 + nt * 8]);
                uint32_t bl0 = __float_as_uint(wl[rB + nt * 8]);
                uint32_t bl1 = __float_as_uint(wl[rB + 96 + nt * 8]);
                mma8(acc0[nt], ah0, ah1, ah2, ah3, bh0, bh1);
                mma8(acc0[nt], ah0, ah1, ah2, ah3, bl0, bl1);
                mma8(acc1[nt], gh0, gh1, gh2, gh3, bh0, bh1);
                mma8(acc1[nt], gh0, gh1, gh2, gh3, bl0, bl1);
            }
        }
    }

    int yA = ty + 2 * w, xA = tx + gid, xB = xA + 8;
    size_t bb = (size_t)b * 18 * 16384;
#pragma unroll
    for (int nt = 0; nt < 3; nt++) {
        int o0 = nt * 8 + 2 * tig;
        if (o0 < 18) {
            float bs = ob[o0];
            float* pl = g_off + bb + (size_t)o0 * 16384;
            pl[yA * 128 + xA]       = acc0[nt][0] + bs;
            pl[yA * 128 + xB]       = acc0[nt][2] + bs;
            pl[(yA + 1) * 128 + xA] = acc1[nt][0] + bs;
            pl[(yA + 1) * 128 + xB] = acc1[nt][2] + bs;
        }
        if (o0 + 1 < 18) {
            float bs = ob[o0 + 1];
            float* pl = g_off + bb + (size_t)(o0 + 1) * 16384;
            pl[yA * 128 + xA]       = acc0[nt][1] + bs;
            pl[yA * 128 + xB]       = acc0[nt][3] + bs;
            pl[(yA + 1) * 128 + xA] = acc1[nt][1] + bs;
            pl[(yA + 1) * 128 + xB] = acc1[nt][3] + bs;
        }
    }
}

// ===================== SMEM layout main (floats) =====================
#define SM_WYX 0
#define SM_SPP 4608
#define SM_XT  9216
#define SM_WHI 16176
#define SMEM_MAIN_BYTES (21072 * 4)

// ===================== stage 2: gather + tf32 mma (A 2-split) ==============
// Block 16x16 pixels (M=256), 8 warps x 32 pixels. N=64. K tap-major, 8ch/chunk.
__global__ __launch_bounds__(256) void deform_main_kernel(
    const float* __restrict__ x, const float* __restrict__ db,
    float* __restrict__ out)
{
    extern __shared__ __align__(16) float smf[];
    float2* swyx = (float2*)(smf + SM_WYX);
    int2*   spp  = (int2*)(smf + SM_SPP);
    float*  xt   = smf + SM_XT;          // 8ch x 29x30 (halo 6)
    float*  whs  = smf + SM_WHI;         // [kk][68] permuted

    int tid = threadIdx.x, w = tid >> 5, lane = tid & 31;
    int gid = lane >> 2, tig = lane & 3;
    int b = blockIdx.z, ty = blockIdx.y * 16, tx = blockIdx.x * 16;
    const float* xb = x + (size_t)b * 64 * 16384;

    // ---- prologue: per (tap,pixel) metadata ----
    for (int e = tid; e < 2304; e += 256) {
        int k = e >> 8, p = e & 255;
        int yy = ty + (p >> 4), xx = tx + (p & 15);
        float dy = g_off[((size_t)b * 18 + 2 * k) * 16384 + yy * 128 + xx];
        float dx = g_off[((size_t)b * 18 + 2 * k + 1) * 16384 + yy * 128 + xx];
        float py = (float)(yy + k / 3 - 1) + dy;
        float px = (float)(xx + k % 3 - 1) + dx;
        float fy = floorf(py), fx = floorf(px);
        float wy = py - fy, wx = px - fx;
        fy = fminf(fmaxf(fy, -1000.f), 1000.f);
        fx = fminf(fmaxf(fx, -1000.f), 1000.f);
        int iy = (int)fy, ix = (int)fx;
        int ly = iy - (ty - 6), lx = ix - (tx - 6);
        int toff = ((unsigned)ly < 28u && (unsigned)lx < 29u) ? (ly * 30 + lx) : -1;
        int pk = ((iy + 1024) << 16) | ((ix + 1024) & 0xffff);
        swyx[e] = make_float2(wy, wx);
        spp[e] = make_int2(toff, pk);
    }

    float acc0[8][4], acc1[8][4];
#pragma unroll
    for (int n = 0; n < 8; n++)
#pragma unroll
        for (int i = 0; i < 4; i++) { acc0[n][i] = 0.f; acc1[n][i] = 0.f; }

    const int p0 = w * 32 + gid;

    for (int j = 0; j < 8; j++) {
        __syncthreads();
        const float* xc = xb + (size_t)j * 8 * 16384;
        for (int t = tid; t < 6960; t += 256) {
            int cc = t / 870, r = t - cc * 870;
            int rr = r / 30, cl = r - rr * 30;
            int gy = ty - 6 + rr, gx = tx - 6 + cl;
            float v = 0.f;
            if ((unsigned)gy < 128u && (unsigned)gx < 128u)
                v = xc[cc * 16384 + gy * 128 + gx];
            xt[t] = v;
        }
        {
            const float4* src = (const float4*)(g_whi + j * 4608);
            for (int t = tid; t < 1152; t += 256) {
                int kk = t >> 4, q4 = t & 15;
                *(float4*)(whs + kk * 68 + q4 * 4) = src[t];
            }
        }
        __syncthreads();

        const float* xtc0 = xt + tig * 870;
        const float* xtc1 = xtc0 + 4 * 870;
        const float* xg0 = xc + (size_t)tig * 16384;
        const float* xg1 = xg0 + 4 * 16384;

#pragma unroll
        for (int kt = 0; kt < 9; kt++) {
            int ib = kt * 256 + p0;
            float2 m0 = swyx[ib];      int2 q0 = spp[ib];
            float2 m1 = swyx[ib + 8];  int2 q1 = spp[ib + 8];
            float2 m2 = swyx[ib + 16]; int2 q2 = spp[ib + 16];
            float2 m3 = swyx[ib + 24]; int2 q3 = spp[ib + 24];
            float a00, a01, a10, a11, b00, b01, b10, b11, c00, c01, c10, c11, d00, d01, d10, d11;
            bilw(m0, a00, a01, a10, a11);
            bilw(m1, b00, b01, b10, b11);
            bilw(m2, c00, c01, c10, c11);
            bilw(m3, d00, d01, d10, d11);

            float s00 = bsample(xtc0, xg0, q0.x, q0.y, a00, a01, a10, a11);
            float s01 = bsample(xtc0, xg0, q1.x, q1.y, b00, b01, b10, b11);
            float s02 = bsample(xtc0, xg0, q2.x, q2.y, c00, c01, c10, c11);
            float s03 = bsample(xtc0, xg0, q3.x, q3.y, d00, d01, d10, d11);
            float s10 = bsample(xtc1, xg1, q0.x, q0.y, a00, a01, a10, a11);
            float s11 = bsample(xtc1, xg1, q1.x, q1.y, b00, b01, b10, b11);
            float s12 = bsample(xtc1, xg1, q2.x, q2.y, c00, c01, c10, c11);
            float s13 = bsample(xtc1, xg1, q3.x, q3.y, d00, d01, d10, d11);

            uint32_t ah0 = f2tf32(s00), ah1 = f2tf32(s01);
            uint32_t ah2 = f2tf32(s10), ah3 = f2tf32(s11);
            uint32_t gh0 = f2tf32(s02), gh1 = f2tf32(s03);
            uint32_t gh2 = f2tf32(s12), gh3 = f2tf32(s13);
            uint32_t al0 = f2tf32(s00 - __uint_as_float(ah0));
            uint32_t al1 = f2tf32(s01 - __uint_as_float(ah1));
            uint32_t al2 = f2tf32(s10 - __uint_as_float(ah2));
            uint32_t al3 = f2tf32(s11 - __uint_as_float(ah3));
            uint32_t gl0 = f2tf32(s02 - __uint_as_float(gh0));
            uint32_t gl1 = f2tf32(s03 - __uint_as_float(gh1));
            uint32_t gl2 = f2tf32(s12 - __uint_as_float(gh2));
            uint32_t gl3 = f2tf32(s13 - __uint_as_float(gh3));

            int rb = (kt * 8 + tig) * 68 + gid * 8;
            float4 b0a = *(const float4*)(whs + rb);
            float4 b0b = *(const float4*)(whs + rb + 4);
            float4 b1a = *(const float4*)(whs + rb + 272);
            float4 b1b = *(const float4*)(whs + rb + 276);
            uint32_t B0[8] = {
                __float_as_uint(b0a.x), __float_as_uint(b0a.y),
                __float_as_uint(b0a.z), __float_as_uint(b0a.w),
                __float_as_uint(b0b.x), __float_as_uint(b0b.y),
                __float_as_uint(b0b.z), __float_as_uint(b0b.w)};
            uint32_t B1[8] = {
                __float_as_uint(b1a.x), __float_as_uint(b1a.y),
                __float_as_uint(b1a.z), __float_as_uint(b1a.w),
                __float_as_uint(b1b.x), __float_as_uint(b1b.y),
                __float_as_uint(b1b.z), __float_as_uint(b1b.w)};

#pragma unroll
            for (int nt = 0; nt < 8; nt++) {
                mma8(acc0[nt], ah0, ah1, ah2, ah3, B0[nt], B1[nt]);
                mma8(acc0[nt], al0, al1, al2, al3, B0[nt], B1[nt]);
                mma8(acc1[nt], gh0, gh1, gh2, gh3, B0[nt], B1[nt]);
                mma8(acc1[nt], gl0, gl1, gl2, gl3, B0[nt], B1[nt]);
            }
        }
    }

    // ---- epilogue: bias + relu ----
    int yA = ty + 2 * w, xA = tx + gid, xB = xA + 8;
    float* obp = out + (size_t)b * 64 * 16384;
#pragma unroll
    for (int nt = 0; nt < 8; nt++) {
        int o0 = nt * 8 + 2 * tig;
        float bs0 = db[o0], bs1 = db[o0 + 1];
        float* pl0 = obp + (size_t)o0 * 16384;
        float* pl1 = pl0 + 16384;
        pl0[yA * 128 + xA]       = fmaxf(acc0[nt][0] + bs0, 0.f);
        pl1[yA * 128 + xA]       = fmaxf(acc0[nt][1] + bs1, 0.f);
        pl0[yA * 128 + xB]       = fmaxf(acc0[nt][2] + bs0, 0.f);
        pl1[yA * 128 + xB]       = fmaxf(acc0[nt][3] + bs1, 0.f);
        pl0[(yA + 1) * 128 + xA] = fmaxf(acc1[nt][0] + bs0, 0.f);
        pl1[(yA + 1) * 128 + xA] = fmaxf(acc1[nt][1] + bs1, 0.f);
        pl0[(yA + 1) * 128 + xB] = fmaxf(acc1[nt][2] + bs0, 0.f);
        pl1[(yA + 1) * 128 + xB] = fmaxf(acc1[nt][3] + bs1, 0.f);
    }
}

// ===================== launch =====================
extern "C" void kernel_launch(void* const* d_in, const int* in_sizes, int n_in,
                              void* d_out, int out_size) {
    const float* x        = (const float*)d_in[0];  // (8,64,128,128)
    const float* offset_w = (const float*)d_in[1];  // (18,64,3,3)
    const float* offset_b = (const float*)d_in[2];  // (18,)
    const float* deform_w = (const float*)d_in[3];  // (64,64,3,3)
    const float* deform_b = (const float*)d_in[4];  // (64,)
    float* out = (float*)d_out;                     // (8,64,128,128)

    cudaFuncSetAttribute(deform_main_kernel,
                         cudaFuncAttributeMaxDynamicSharedMemorySize,
                         SMEM_MAIN_BYTES);

    wprep_kernel<<<144, 256>>>(deform_w, offset_w);
    offconv_kernel<<<dim3(8, 8, 8), 256>>>(x, offset_b);
    deform_main_kernel<<<dim3(8, 8, 8), 256, SMEM_MAIN_BYTES>>>(x, deform_b, out);
}

// round 5
// speedup vs baseline: 2.1955x; 1.0784x over previous
#include <cuda_runtime.h>
#include <cstdint>

// ===================== device scratch (no allocation) =====================
__device__ float g_off[8 * 18 * 128 * 128];   // offset conv output
__device__ float g_whi[8 * 72 * 64];          // main W tf32: [j][kk=tap*8+s][q]
__device__ float g_owhi[8 * 72 * 32];         // offset W tf32: [j][kk][gid*4+nt]

// ===================== helpers =====================
__device__ __forceinline__ uint32_t f2tf32(float f) {
    uint32_t r;
    asm("cvt.rna.tf32.f32 %0, %1;" : "=r"(r) : "f"(f));
    return r;
}
__device__ __forceinline__ void mma8(float* d,
                                     uint32_t a0, uint32_t a1, uint32_t a2, uint32_t a3,
                                     uint32_t b0, uint32_t b1) {
    asm volatile(
        "mma.sync.aligned.m16n8k8.row.col.f32.tf32.tf32.f32 "
        "{%0,%1,%2,%3}, {%4,%5,%6,%7}, {%8,%9}, {%0,%1,%2,%3};"
        : "+f"(d[0]), "+f"(d[1]), "+f"(d[2]), "+f"(d[3])
        : "r"(a0), "r"(a1), "r"(a2), "r"(a3), "r"(b0), "r"(b1));
}

// bilinear sample of a channel PAIR; interior -> float2 smem tile (stride 30)
__device__ __forceinline__ float2 bsample2(const float2* __restrict__ xt_cp,
                                           const float* __restrict__ xg0,
                                           const float* __restrict__ xg1,
                                           int val,
                                           float w00, float w01, float w10, float w11) {
    if (val >= 0) {
        float2 c0 = xt_cp[val], c1 = xt_cp[val + 1];
        float2 c2 = xt_cp[val + 30], c3 = xt_cp[val + 31];
        float vx = w00 * c0.x + w01 * c1.x + w10 * c2.x + w11 * c3.x;
        float vy = w00 * c0.y + w01 * c1.y + w10 * c2.y + w11 * c3.y;
        return make_float2(vx, vy);
    }
    int iy = ((val >> 8) & 0xff) - 2;
    int ix = (val & 0xff) - 2;
    bool m00 = ((unsigned)iy < 128u) & ((unsigned)ix < 128u);
    bool m01 = ((unsigned)iy < 128u) & ((unsigned)(ix + 1) < 128u);
    bool m10 = ((unsigned)(iy + 1) < 128u) & ((unsigned)ix < 128u);
    bool m11 = ((unsigned)(iy + 1) < 128u) & ((unsigned)(ix + 1) < 128u);
    int i00 = iy * 128 + ix;
    float vx = w00 * (m00 ? xg0[i00] : 0.f) + w01 * (m01 ? xg0[i00 + 1] : 0.f)
             + w10 * (m10 ? xg0[i00 + 128] : 0.f) + w11 * (m11 ? xg0[i00 + 129] : 0.f);
    float vy = w00 * (m00 ? xg1[i00] : 0.f) + w01 * (m01 ? xg1[i00 + 1] : 0.f)
             + w10 * (m10 ? xg1[i00 + 128] : 0.f) + w11 * (m11 ? xg1[i00 + 129] : 0.f);
    return make_float2(vx, vy);
}

// ===================== prep: weight layouts =====================
// k-slot s within a chunk holds channel 2*(s&3) + (s>>2)  (pairs lanes' slots)
__global__ void wprep_kernel(const float* __restrict__ dw,
                             const float* __restrict__ ow) {
    int i = blockIdx.x * 256 + threadIdx.x;
    if (i < 36864) {           // main W
        int j = i / 4608, r = i - j * 4608;
        int kk = r >> 6, q = r & 63;
        int tap = kk >> 3, s = kk & 7;
        int c = j * 8 + 2 * (s & 3) + (s >> 2);
        int o = (q & 7) * 8 + (q >> 3);
        g_whi[i] = __uint_as_float(f2tf32(dw[o * 576 + c * 9 + tap]));
    }
    if (i < 18432) {           // offset W: [j][kk][gid*4+nt]
        int j = i / 2304, r = i - j * 2304;
        int kk = r >> 5, col = r & 31;
        int tap = kk >> 3, s = kk & 7;
        int c = j * 8 + 2 * (s & 3) + (s >> 2);
        int nt = col & 3, g = col >> 2;
        int o = nt * 8 + g;
        float wv = (nt < 3 && o < 18) ? ow[o * 576 + c * 9 + tap] : 0.f;
        g_owhi[i] = __uint_as_float(f2tf32(wv));
    }
}

// ===================== stage 1: offset conv via mma (tf32) =====================
// Block 16x16 pixels, 8 warps. N=24 (18 used). x tile pre-rounded to tf32.
__global__ __launch_bounds__(256) void offconv_kernel(
    const float* __restrict__ x, const float* __restrict__ ob)
{
    __shared__ float2 xt2[1296];        // 4 cpairs x 18x18 (halo 1)
    __shared__ float wh[2304];          // [kk][32]

    int tid = threadIdx.x, w = tid >> 5, lane = tid & 31;
    int gid = lane >> 2, tig = lane & 3;
    int b = blockIdx.z, ty = blockIdx.y * 16, tx = blockIdx.x * 16;
    const float* xb = x + (size_t)b * 64 * 16384;

    float acc0[3][4], acc1[3][4];
#pragma unroll
    for (int n = 0; n < 3; n++)
#pragma unroll
        for (int i = 0; i < 4; i++) { acc0[n][i] = 0.f; acc1[n][i] = 0.f; }

    for (int j = 0; j < 8; j++) {
        __syncthreads();
        const float* xc = xb + (size_t)j * 8 * 16384;
        for (int t = tid; t < 1296; t += 256) {
            int cp = t / 324, pos = t - cp * 324;
            int rr = pos / 18, cl = pos - rr * 18;
            int gy = ty - 1 + rr, gx = tx - 1 + cl;
            float2 v = make_float2(0.f, 0.f);
            if ((unsigned)gy < 128u && (unsigned)gx < 128u) {
                const float* s = xc + 2 * cp * 16384 + gy * 128 + gx;
                v.x = __uint_as_float(f2tf32(s[0]));
                v.y = __uint_as_float(f2tf32(s[16384]));
            }
            xt2[t] = v;
        }
        for (int t = tid; t < 2304; t += 256) wh[t] = g_owhi[j * 2304 + t];
        __syncthreads();

#pragma unroll
        for (int kt = 0; kt < 9; kt++) {
            int dty = kt / 3, dtx = kt - dty * 3;
            const float2* ap = xt2 + tig * 324 + (2 * w + dty) * 18 + gid + dtx;
            float2 f0 = ap[0], f1 = ap[8], f2v = ap[18], f3 = ap[26];
            float4 bA = *(const float4*)(wh + (kt * 8 + tig) * 32 + gid * 4);
            float4 bB = *(const float4*)(wh + (kt * 8 + tig + 4) * 32 + gid * 4);
            uint32_t a0 = __float_as_uint(f0.x), a1 = __float_as_uint(f1.x);
            uint32_t a2 = __float_as_uint(f0.y), a3 = __float_as_uint(f1.y);
            uint32_t g0 = __float_as_uint(f2v.x), g1 = __float_as_uint(f3.x);
            uint32_t g2 = __float_as_uint(f2v.y), g3 = __float_as_uint(f3.y);
            mma8(acc0[0], a0, a1, a2, a3, __float_as_uint(bA.x), __float_as_uint(bB.x));
            mma8(acc0[1], a0, a1, a2, a3, __float_as_uint(bA.y), __float_as_uint(bB.y));
            mma8(acc0[2], a0, a1, a2, a3, __float_as_uint(bA.z), __float_as_uint(bB.z));
            mma8(acc1[0], g0, g1, g2, g3, __float_as_uint(bA.x), __float_as_uint(bB.x));
            mma8(acc1[1], g0, g1, g2, g3, __float_as_uint(bA.y), __float_as_uint(bB.y));
            mma8(acc1[2], g0, g1, g2, g3, __float_as_uint(bA.z), __float_as_uint(bB.z));
        }
    }

    int yA = ty + 2 * w, xA = tx + gid, xB = xA + 8;
    size_t bb = (size_t)b * 18 * 16384;
#pragma unroll
    for (int nt = 0; nt < 3; nt++) {
        int o0 = nt * 8 + 2 * tig;
        if (o0 < 18) {
            float bs = ob[o0];
            float* pl = g_off + bb + (size_t)o0 * 16384;
            pl[yA * 128 + xA]       = acc0[nt][0] + bs;
            pl[yA * 128 + xB]       = acc0[nt][2] + bs;
            pl[(yA + 1) * 128 + xA] = acc1[nt][0] + bs;
            pl[(yA + 1) * 128 + xB] = acc1[nt][2] + bs;
        }
        if (o0 + 1 < 18) {
            float bs = ob[o0 + 1];
            float* pl = g_off + bb + (size_t)(o0 + 1) * 16384;
            pl[yA * 128 + xA]       = acc0[nt][1] + bs;
            pl[yA * 128 + xB]       = acc0[nt][3] + bs;
            pl[(yA + 1) * 128 + xA] = acc1[nt][1] + bs;
            pl[(yA + 1) * 128 + xB] = acc1[nt][3] + bs;
        }
    }
}

// ===================== SMEM layout main (float index) =====================
#define SM_WYX 0
#define SM_SPK 4608
#define SM_XT  6912
#define SM_WHI 13872
#define SMEM_MAIN_BYTES (18768 * 4)

// ===================== stage 2: gather + tf32 mma (A hi only) ==============
// Block 16x16 pixels (M=256), 8 warps x 32 pixels. N=64. K tap-major, 8ch/chunk.
__global__ __launch_bounds__(256) void deform_main_kernel(
    const float* __restrict__ x, const float* __restrict__ db,
    float* __restrict__ out)
{
    extern __shared__ __align__(16) float smf[];
    float2* swyx = (float2*)(smf + SM_WYX);     // 2304 x float2
    int*    spk  = (int*)(smf + SM_SPK);        // 2304 packed
    float2* xt2  = (float2*)(smf + SM_XT);      // 4 cpairs x 29x30
    float*  whs  = smf + SM_WHI;                // [72][68]

    int tid = threadIdx.x, w = tid >> 5, lane = tid & 31;
    int gid = lane >> 2, tig = lane & 3;
    int b = blockIdx.z, ty = blockIdx.y * 16, tx = blockIdx.x * 16;
    const float* xb = x + (size_t)b * 64 * 16384;

    // ---- prologue: per (tap,pixel) metadata ----
    for (int e = tid; e < 2304; e += 256) {
        int k = e >> 8, p = e & 255;
        int yy = ty + (p >> 4), xx = tx + (p & 15);
        float dy = g_off[((size_t)b * 18 + 2 * k) * 16384 + yy * 128 + xx];
        float dx = g_off[((size_t)b * 18 + 2 * k + 1) * 16384 + yy * 128 + xx];
        float py = (float)(yy + k / 3 - 1) + dy;
        float px = (float)(xx + k % 3 - 1) + dx;
        float fy = floorf(py), fx = floorf(px);
        float wy = py - fy, wx = px - fx;
        // clamp to [-2,128]: clamped region has all-invalid corners -> exact 0
        int iy = (int)fminf(fmaxf(fy, -2.f), 128.f);
        int ix = (int)fminf(fmaxf(fx, -2.f), 128.f);
        int ly = iy - (ty - 6), lx = ix - (tx - 6);
        int val;
        if ((unsigned)ly < 28u && (unsigned)lx < 29u)
            val = ly * 30 + lx;
        else
            val = (int)(0x80000000u | ((unsigned)(iy + 2) << 8) | (unsigned)(ix + 2));
        swyx[e] = make_float2(wy, wx);
        spk[e] = val;
    }

    float acc0[8][4], acc1[8][4];
#pragma unroll
    for (int n = 0; n < 8; n++)
#pragma unroll
        for (int i = 0; i < 4; i++) { acc0[n][i] = 0.f; acc1[n][i] = 0.f; }

    const int p0 = w * 32 + gid;

    for (int j = 0; j < 8; j++) {
        __syncthreads();
        const float* xc = xb + (size_t)j * 8 * 16384;
        // x tile: 4 channel pairs x 29x30 (halo 6), float2
        for (int t = tid; t < 3480; t += 256) {
            int cp = t / 870, pos = t - cp * 870;
            int rr = pos / 30, cl = pos - rr * 30;
            int gy = ty - 6 + rr, gx = tx - 6 + cl;
            float2 v = make_float2(0.f, 0.f);
            if ((unsigned)gy < 128u && (unsigned)gx < 128u) {
                const float* s = xc + 2 * cp * 16384 + gy * 128 + gx;
                v.x = s[0];
                v.y = s[16384];
            }
            xt2[t] = v;
        }
        {
            const float4* src = (const float4*)(g_whi + j * 4608);
            for (int t = tid; t < 1152; t += 256) {
                int kk = t >> 4, q4 = t & 15;
                *(float4*)(whs + kk * 68 + q4 * 4) = src[t];
            }
        }
        __syncthreads();

        const float2* xtc = xt2 + tig * 870;
        const float* xg0 = xc + (size_t)(2 * tig) * 16384;
        const float* xg1 = xg0 + 16384;

#pragma unroll
        for (int kt = 0; kt < 9; kt++) {
            int ib = kt * 256 + p0;
            float2 m0 = swyx[ib];      int q0 = spk[ib];
            float2 m1 = swyx[ib + 8];  int q1 = spk[ib + 8];
            float2 m2 = swyx[ib + 16]; int q2 = spk[ib + 16];
            float2 m3 = swyx[ib + 24]; int q3 = spk[ib + 24];

            float oy, ox;
            oy = 1.f - m0.x; ox = 1.f - m0.y;
            float2 s0 = bsample2(xtc, xg0, xg1, q0, oy * ox, oy * m0.y, m0.x * ox, m0.x * m0.y);
            oy = 1.f - m1.x; ox = 1.f - m1.y;
            float2 s1 = bsample2(xtc, xg0, xg1, q1, oy * ox, oy * m1.y, m1.x * ox, m1.x * m1.y);
            oy = 1.f - m2.x; ox = 1.f - m2.y;
            float2 s2 = bsample2(xtc, xg0, xg1, q2, oy * ox, oy * m2.y, m2.x * ox, m2.x * m2.y);
            oy = 1.f - m3.x; ox = 1.f - m3.y;
            float2 s3 = bsample2(xtc, xg0, xg1, q3, oy * ox, oy * m3.y, m3.x * ox, m3.x * m3.y);

            uint32_t a0 = f2tf32(s0.x), a1 = f2tf32(s1.x);
            uint32_t a2 = f2tf32(s0.y), a3 = f2tf32(s1.y);
            uint32_t g0 = f2tf32(s2.x), g1 = f2tf32(s3.x);
            uint32_t g2 = f2tf32(s2.y), g3 = f2tf32(s3.y);

            int rb = (kt * 8 + tig) * 68 + gid * 8;
            float4 b0a = *(const float4*)(whs + rb);
            float4 b0b = *(const float4*)(whs + rb + 4);
            float4 b1a = *(const float4*)(whs + rb + 272);
            float4 b1b = *(const float4*)(whs + rb + 276);
            uint32_t B0[8] = {
                __float_as_uint(b0a.x), __float_as_uint(b0a.y),
                __float_as_uint(b0a.z), __float_as_uint(b0a.w),
                __float_as_uint(b0b.x), __float_as_uint(b0b.y),
                __float_as_uint(b0b.z), __float_as_uint(b0b.w)};
            uint32_t B1[8] = {
                __float_as_uint(b1a.x), __float_as_uint(b1a.y),
                __float_as_uint(b1a.z), __float_as_uint(b1a.w),
                __float_as_uint(b1b.x), __float_as_uint(b1b.y),
                __float_as_uint(b1b.z), __float_as_uint(b1b.w)};

#pragma unroll
            for (int nt = 0; nt < 8; nt++) {
                mma8(acc0[nt], a0, a1, a2, a3, B0[nt], B1[nt]);
                mma8(acc1[nt], g0, g1, g2, g3, B0[nt], B1[nt]);
            }
        }
    }

    // ---- epilogue: bias + relu ----
    int yA = ty + 2 * w, xA = tx + gid, xB = xA + 8;
    float* obp = out + (size_t)b * 64 * 16384;
#pragma unroll
    for (int nt = 0; nt < 8; nt++) {
        int o0 = nt * 8 + 2 * tig;
        float bs0 = db[o0], bs1 = db[o0 + 1];
        float* pl0 = obp + (size_t)o0 * 16384;
        float* pl1 = pl0 + 16384;
        pl0[yA * 128 + xA]       = fmaxf(acc0[nt][0] + bs0, 0.f);
        pl1[yA * 128 + xA]       = fmaxf(acc0[nt][1] + bs1, 0.f);
        pl0[yA * 128 + xB]       = fmaxf(acc0[nt][2] + bs0, 0.f);
        pl1[yA * 128 + xB]       = fmaxf(acc0[nt][3] + bs1, 0.f);
        pl0[(yA + 1) * 128 + xA] = fmaxf(acc1[nt][0] + bs0, 0.f);
        pl1[(yA + 1) * 128 + xA] = fmaxf(acc1[nt][1] + bs1, 0.f);
        pl0[(yA + 1) * 128 + xB] = fmaxf(acc1[nt][2] + bs0, 0.f);
        pl1[(yA + 1) * 128 + xB] = fmaxf(acc1[nt][3] + bs1, 0.f);
    }
}

// ===================== launch =====================
extern "C" void kernel_launch(void* const* d_in, const int* in_sizes, int n_in,
                              void* d_out, int out_size) {
    const float* x        = (const float*)d_in[0];  // (8,64,128,128)
    const float* offset_w = (const float*)d_in[1];  // (18,64,3,3)
    const float* offset_b = (const float*)d_in[2];  // (18,)
    const float* deform_w = (const float*)d_in[3];  // (64,64,3,3)
    const float* deform_b = (const float*)d_in[4];  // (64,)
    float* out = (float*)d_out;                     // (8,64,128,128)

    cudaFuncSetAttribute(deform_main_kernel,
                         cudaFuncAttributeMaxDynamicSharedMemorySize,
                         SMEM_MAIN_BYTES);

    wprep_kernel<<<144, 256>>>(deform_w, offset_w);
    offconv_kernel<<<dim3(8, 8, 8), 256>>>(x, offset_b);
    deform_main_kernel<<<dim3(8, 8, 8), 256, SMEM_MAIN_BYTES>>>(x, deform_b, out);
}